// round 1
// baseline (speedup 1.0000x reference)
#include <cuda_runtime.h>

#define BW 512     // B*W
#define NN 128     // nodes
#define FF 128     // features
#define CC 512     // H*F

__device__ float g_h0[BW * FF];
__device__ float g_r[BW * CC];
__device__ float g_part[4 * BW * NN];

#define LDS_ 132   // padded row stride (floats); 132*4B = 528B, 16B-aligned, odd in 16B units

// Generic small GEMM: C[M x N] = A[M x 128] * B, K fixed = 128 (fits in smem, no k-loop).
// BT=false: B is [128 x n] row-major (normal), transposed into smem.
// BT=true : B rows are the "n" dim: C[m][n] = sum_f A[m][f] * B[n][f].
// blockIdx.z = split-K chunk (shifts A cols by z*128, B rows by z*128, C by z*BW*NN).
// EPI: 0 = +bias, 1 = relu, 2 = plain store.
template<int EPI, bool BT>
__global__ void gemm128(const float* __restrict__ A, int ldA,
                        const float* __restrict__ B, int ldB,
                        const float* __restrict__ bias,
                        float* __restrict__ C, int ldC)
{
    extern __shared__ float sm[];
    float* As = sm;               // 32 x LDS_
    float* Bs = sm + 32 * LDS_;   // 64 x LDS_  (row = n_local, col = k)
    const int tid = threadIdx.x;  // 128 threads
    const int m0 = blockIdx.x * 32, n0 = blockIdx.y * 64;
    const int z = blockIdx.z;
    A += z * 128;
    if (!BT) B += (size_t)z * 128 * ldB;
    C += (size_t)z * (BW * NN);

    // Load A tile: 32 rows x 128 cols = 1024 float4
    #pragma unroll
    for (int i = 0; i < 8; i++) {
        int idx = tid + i * 128;
        int r = idx >> 5, c4 = idx & 31;
        float4 v = *(const float4*)(A + (size_t)(m0 + r) * ldA + c4 * 4);
        *(float4*)(As + r * LDS_ + c4 * 4) = v;
    }
    // Load B tile
    if (BT) {
        #pragma unroll
        for (int i = 0; i < 16; i++) {
            int idx = tid + i * 128;
            int r = idx >> 5, c4 = idx & 31;
            float4 v = *(const float4*)(B + (size_t)(n0 + r) * ldB + c4 * 4);
            *(float4*)(Bs + r * LDS_ + c4 * 4) = v;
        }
    } else {
        // transpose on store: Bs[n_local][k] = B[k][n0+n_local]
        #pragma unroll
        for (int i = 0; i < 16; i++) {
            int idx = tid + i * 128;
            int kk = idx >> 4, nn4 = idx & 15;
            float4 v = *(const float4*)(B + (size_t)kk * ldB + n0 + nn4 * 4);
            Bs[(nn4 * 4 + 0) * LDS_ + kk] = v.x;
            Bs[(nn4 * 4 + 1) * LDS_ + kk] = v.y;
            Bs[(nn4 * 4 + 2) * LDS_ + kk] = v.z;
            Bs[(nn4 * 4 + 3) * LDS_ + kk] = v.w;
        }
    }
    __syncthreads();

    const int tx = tid & 15, ty = tid >> 4;   // n = n0 + tx + 16j, m = m0 + ty + 8i
    float acc[4][4];
    #pragma unroll
    for (int i = 0; i < 4; i++)
        #pragma unroll
        for (int j = 0; j < 4; j++) acc[i][j] = 0.f;

    #pragma unroll 8
    for (int f4 = 0; f4 < 32; f4++) {
        float4 a[4], b[4];
        #pragma unroll
        for (int i = 0; i < 4; i++) a[i] = *(const float4*)(As + (ty + 8 * i) * LDS_ + f4 * 4);
        #pragma unroll
        for (int j = 0; j < 4; j++) b[j] = *(const float4*)(Bs + (tx + 16 * j) * LDS_ + f4 * 4);
        #pragma unroll
        for (int i = 0; i < 4; i++)
            #pragma unroll
            for (int j = 0; j < 4; j++) {
                acc[i][j] += a[i].x * b[j].x;
                acc[i][j] += a[i].y * b[j].y;
                acc[i][j] += a[i].z * b[j].z;
                acc[i][j] += a[i].w * b[j].w;
            }
    }

    #pragma unroll
    for (int i = 0; i < 4; i++) {
        int m = m0 + ty + 8 * i;
        #pragma unroll
        for (int j = 0; j < 4; j++) {
            int n = n0 + tx + 16 * j;
            float v = acc[i][j];
            if (EPI == 0) v += bias[n];
            if (EPI == 1) v = fmaxf(v, 0.f);
            C[(size_t)m * ldC + n] = v;
        }
    }
}

// t = sum of 4 split-K partials + op_b; out = x*(1-mask) + t*mask
__global__ void final_kernel(const float* __restrict__ x, const float* __restrict__ mask,
                             const float* __restrict__ opb, const float* __restrict__ part,
                             float* __restrict__ out)
{
    int idx = blockIdx.x * 256 + threadIdx.x;   // 65536 total
    int n = idx & 127;
    float t = part[idx] + part[65536 + idx] + part[2 * 65536 + idx] + part[3 * 65536 + idx] + opb[n];
    float xv = x[idx], mv = mask[idx];
    out[idx] = xv * (1.0f - mv) + t * mv;
}

// adj: cosine similarity top-k (stable, lower index wins ties) per row.
// One block per row i, thread j handles column j.
__global__ void adj_kernel(const float* __restrict__ emb, const int* __restrict__ kp,
                           float* __restrict__ adj_out)
{
    extern __shared__ float es[];           // 128 x LDS_
    __shared__ float s_sim[128];
    __shared__ float s_n2[128];
    const int i = blockIdx.x, j = threadIdx.x;

    #pragma unroll
    for (int t = 0; t < 32; t++) {
        int idx = j + t * 128;
        int r = idx >> 5, c4 = idx & 31;
        float4 v = *(const float4*)(emb + (size_t)r * 128 + c4 * 4);
        *(float4*)(es + r * LDS_ + c4 * 4) = v;
    }
    __syncthreads();

    float dij = 0.f, njj = 0.f;
    #pragma unroll 8
    for (int f4 = 0; f4 < 32; f4++) {
        float4 a = *(const float4*)(es + i * LDS_ + f4 * 4);
        float4 b = *(const float4*)(es + j * LDS_ + f4 * 4);
        dij += a.x * b.x + a.y * b.y + a.z * b.z + a.w * b.w;
        njj += b.x * b.x + b.y * b.y + b.z * b.z + b.w * b.w;
    }
    s_n2[j] = njj;
    __syncthreads();
    float sim = dij / (sqrtf(s_n2[i]) * sqrtf(s_n2[j]));
    s_sim[j] = sim;
    __syncthreads();

    int cnt = 0;
    const float sj = sim;
    #pragma unroll 8
    for (int jj = 0; jj < 128; jj++) {
        float s2 = s_sim[jj];
        cnt += (s2 > sj) || (s2 == sj && jj < j);
    }
    adj_out[i * 128 + j] = (cnt < kp[0]) ? 1.0f : 0.0f;
}

extern "C" void kernel_launch(void* const* d_in, const int* in_sizes, int n_in,
                              void* d_out, int out_size)
{
    const float* x    = (const float*)d_in[0];
    const float* mask = (const float*)d_in[1];
    const float* emb  = (const float*)d_in[2];
    const float* gatW = (const float*)d_in[3];   // (H,F,F) == rows c=(h*F+o) x 128 f
    // d_in[4] = gat_a: provably unused (softmax collapses to adj/k)
    const float* fpW  = (const float*)d_in[5];
    const float* fpb  = (const float*)d_in[6];
    const float* opW  = (const float*)d_in[7];
    const float* opb  = (const float*)d_in[8];
    const int*   kp   = (const int*)d_in[9];
    float* out = (float*)d_out;

    float *p_h0, *p_r, *p_part;
    cudaGetSymbolAddress((void**)&p_h0, g_h0);
    cudaGetSymbolAddress((void**)&p_r, g_r);
    cudaGetSymbolAddress((void**)&p_part, g_part);

    const int SMG = (32 + 64) * LDS_ * 4;    // 50688 B
    const int SMA = 128 * LDS_ * 4;          // 67584 B
    cudaFuncSetAttribute(gemm128<0, false>, cudaFuncAttributeMaxDynamicSharedMemorySize, SMG);
    cudaFuncSetAttribute(gemm128<1, true >, cudaFuncAttributeMaxDynamicSharedMemorySize, SMG);
    cudaFuncSetAttribute(gemm128<2, false>, cudaFuncAttributeMaxDynamicSharedMemorySize, SMG);
    cudaFuncSetAttribute(adj_kernel, cudaFuncAttributeMaxDynamicSharedMemorySize, SMA);

    // h0 = x @ fp_W + fp_b            (512x128, K=128)
    gemm128<0, false><<<dim3(16, 2, 1), 128, SMG>>>(x, 128, fpW, 128, fpb, p_h0, 128);
    // r = relu(h0 @ gat_W^T)          (512x512, K=128), gat_W rows are output cols
    gemm128<1, true ><<<dim3(16, 8, 1), 128, SMG>>>(p_h0, 128, gatW, 128, nullptr, p_r, 512);
    // partial[z] = r[:, z*128:+128] @ op_W[z*128:+128, :]   (split-K over 512)
    gemm128<2, false><<<dim3(16, 2, 4), 128, SMG>>>(p_r, 512, opW, 128, nullptr, p_part, 128);
    // out = x*(1-mask) + (sum partials + op_b)*mask
    final_kernel<<<256, 256>>>(x, mask, opb, p_part, out);
    // adj (independent of the chain; written after the 65536 output floats)
    adj_kernel<<<128, 128, SMA>>>(emb, kp, out + BW * NN);
}